// round 10
// baseline (speedup 1.0000x reference)
#include <cuda_runtime.h>
#include <cstdint>

#define NEG_INF __int_as_float(0xff800000)

static __device__ __forceinline__ float max5(float a, float b, float c, float d, float e) {
    return fmaxf(fmaxf(a, fmaxf(b, c)), fmaxf(d, e));
}

// Hex maxpool, SIZE=2, STRIDE=1, plane = 256x256 fp32.
//   even w: col w rows [h-2,h+2]; cols w+-1 rows [h-2,h+1]; cols w+-2 rows [h-1,h+1]
//   odd  w: col w rows [h-2,h+2]; cols w+-1 rows [h-1,h+2]; cols w+-2 rows [h-1,h+1]
//
// One warp per 256-wide strip of 64 rows; lane owns 8 columns.
// Reads : cp.async (LDGSTS) into a 6-row smem ring, 5 rows in flight,
//         rows clamped to [0,255] (== -inf padding for max; verified R8).
// Writes: 3x4KB staging ring; every 8 rows TWO back-to-back 4KB bulk stores
//         to contiguous gmem (8KB effective DRAM write burst, one group).
//         Slot reuse is 5 rows after the group issue -> wait_group 0 at
//         l%8==4 never blocks in steady state.
// 18KB smem/warp = 72KB/CTA -> 3 CTAs/SM (12 warps, inside the measured
// 12-20 warp plateau).
__global__ __launch_bounds__(128, 3)
void hexpool_kernel(const float* __restrict__ x, float* __restrict__ y) {
    __shared__ float inring[4][6][256];                   // 24KB input rings
    __shared__ __align__(16) float ostage[4][3][4][256];  // 48KB store staging

    const int wid  = threadIdx.x >> 5;
    const int lane = threadIdx.x & 31;
    const int warp_global = blockIdx.x * 4 + wid;
    const int img   = warp_global >> 2;   // 1024 planes (N*C)
    const int chunk = warp_global & 3;    // 4 chunks of 64 rows
    const int h0    = chunk * 64;

    const float* __restrict__ inp = x + (size_t)img * 65536;
    const float* __restrict__ inl = inp + lane * 8;
    float* __restrict__ outbase   = y + (size_t)img * 65536;
    float* wring = &inring[wid][0][0];

    // Register window: row m in slot (m+2)&7 (compile-time under 8x unroll).
    float win[8][8];

    // Vertical clamp: substituting the nearest valid row for an OOB row never
    // changes the window max (edge row already belongs to each sub-window).
    auto clamp_row = [&](int m) {
        int g = h0 + m;
        return g < 0 ? 0 : (g > 255 ? 255 : g);
    };

    auto load_row_g = [&](int m, float* dst) {
        const float* p = inl + (size_t)clamp_row(m) * 256;
        const float4 a = *reinterpret_cast<const float4*>(p);
        const float4 b = *reinterpret_cast<const float4*>(p + 4);
        dst[0] = a.x; dst[1] = a.y; dst[2] = a.z; dst[3] = a.w;
        dst[4] = b.x; dst[5] = b.y; dst[6] = b.z; dst[7] = b.w;
    };

    // Prefetch local row r into ring slot r%6 (r<=65; beyond that only the
    // empty commit keeps wait_group counting uniform).
    auto prefetch = [&](int r) {
        if (r <= 65) {
            float* s = wring + (r % 6) * 256 + lane * 8;
            const float* gp = inp + (size_t)clamp_row(r) * 256 + lane * 8;
            uint32_t sa = (uint32_t)__cvta_generic_to_shared(s);
            asm volatile(
                "cp.async.cg.shared.global [%0], [%1], 16;\n\t"
                "cp.async.cg.shared.global [%2], [%3], 16;\n\t"
                :: "r"(sa), "l"(gp), "r"(sa + 16), "l"(gp + 4));
        }
        asm volatile("cp.async.commit_group;");
    };

    auto lds_row = [&](int r, float* dst) {
        const float* s = wring + (r % 6) * 256 + lane * 8;
        const float4 a = *reinterpret_cast<const float4*>(s);
        const float4 b = *reinterpret_cast<const float4*>(s + 4);
        dst[0] = a.x; dst[1] = a.y; dst[2] = a.z; dst[3] = a.w;
        dst[4] = b.x; dst[5] = b.y; dst[6] = b.z; dst[7] = b.w;
    };

    // Prologue: rows -2..2 -> registers; rows 3..7 into the async ring.
    #pragma unroll
    for (int m = -2; m <= 2; ++m) load_row_g(m, win[(m + 2) & 7]);
    #pragma unroll
    for (int r = 3; r <= 7; ++r) prefetch(r);

    for (int hh = 0; hh < 64; hh += 8) {
        #pragma unroll
        for (int u = 0; u < 8; ++u) {
            const int l = hh + u;

            if (u == 4) {
                // Next staging slot belongs to the burst issued at l-5:
                // drain all pending store groups (>=5 rows of slack).
                asm volatile("cp.async.bulk.wait_group 0;");
            }

            // Read pipe: keep rows l+4..l+8 pending, pull row l+3 to regs.
            prefetch(l + 8);
            asm volatile("cp.async.wait_group 5;");
            if (l < 63) lds_row(l + 3, win[(u + 5) & 7]);

            const int s0 = (u + 0) & 7;  // row l-2
            const int s1 = (u + 1) & 7;  // row l-1
            const int sc = (u + 2) & 7;  // row l
            const int s3 = (u + 3) & 7;  // row l+1
            const int s4 = (u + 4) & 7;  // row l+2

            float m3[8], A[8], m5v[8];
            #pragma unroll
            for (int j = 0; j < 8; ++j)
                m3[j] = fmaxf(fmaxf(win[s1][j], win[sc][j]), win[s3][j]);

            // parity of global col = j&1.
            //   odd  w: A = rows [h-2,h+1] = max(m3, r_{l-2})
            //   even w: A = rows [h-1,h+2] = max(m3, r_{l+2})
            //   m5 = 5-row max = max(A, remaining row)
            #pragma unroll
            for (int j = 0; j < 8; ++j) {
                if (j & 1) { A[j]   = fmaxf(m3[j], win[s0][j]);
                             m5v[j] = fmaxf(A[j], win[s4][j]); }
                else       { A[j]   = fmaxf(m3[j], win[s4][j]);
                             m5v[j] = fmaxf(A[j], win[s0][j]); }
            }

            // Horizontal halo across lanes
            float A_l   = __shfl_up_sync(0xffffffffu, A[7], 1);
            float m3_l2 = __shfl_up_sync(0xffffffffu, m3[6], 1);
            float m3_l1 = __shfl_up_sync(0xffffffffu, m3[7], 1);
            float A_r   = __shfl_down_sync(0xffffffffu, A[0], 1);
            float m3_r1 = __shfl_down_sync(0xffffffffu, m3[0], 1);
            float m3_r2 = __shfl_down_sync(0xffffffffu, m3[1], 1);
            if (lane == 0)  { A_l = NEG_INF; m3_l1 = NEG_INF; m3_l2 = NEG_INF; }
            if (lane == 31) { A_r = NEG_INF; m3_r1 = NEG_INF; m3_r2 = NEG_INF; }

            float4 v0, v1;
            v0.x = max5(m5v[0], A_l,  A[1], m3_l2, m3[2]);
            v0.y = max5(m5v[1], A[0], A[2], m3_l1, m3[3]);
            v0.z = max5(m5v[2], A[1], A[3], m3[0], m3[4]);
            v0.w = max5(m5v[3], A[2], A[4], m3[1], m3[5]);
            v1.x = max5(m5v[4], A[3], A[5], m3[2], m3[6]);
            v1.y = max5(m5v[5], A[4], A[6], m3[3], m3[7]);
            v1.z = max5(m5v[6], A[5], A[7], m3[4], m3_r1);
            v1.w = max5(m5v[7], A[6], A_r,  m3[5], m3_r2);

            // Stage the row; slot = (l>>2) % 3 in the 3-buffer ring.
            float* st = &ostage[wid][(l >> 2) % 3][l & 3][lane * 8];
            *reinterpret_cast<float4*>(st)     = v0;
            *reinterpret_cast<float4*>(st + 4) = v1;

            if (u == 7) {
                // Rows l-7..l staged in two ring slots -> two back-to-back
                // 4KB bulk stores to contiguous gmem = 8KB write burst.
                __syncwarp();
                if (lane == 0) {
                    asm volatile("fence.proxy.async.shared::cta;");
                    const int slotA = ((l - 7) >> 2) % 3;   // rows l-7..l-4
                    const int slotB = ((l - 3) >> 2) % 3;   // rows l-3..l
                    uint32_t srcA = (uint32_t)__cvta_generic_to_shared(
                        &ostage[wid][slotA][0][0]);
                    uint32_t srcB = (uint32_t)__cvta_generic_to_shared(
                        &ostage[wid][slotB][0][0]);
                    float* dstA = outbase + (size_t)(h0 + l - 7) * 256;
                    float* dstB = outbase + (size_t)(h0 + l - 3) * 256;
                    asm volatile(
                        "cp.async.bulk.global.shared::cta.bulk_group [%0], [%1], 4096;\n\t"
                        "cp.async.bulk.global.shared::cta.bulk_group [%2], [%3], 4096;\n\t"
                        :: "l"(dstA), "r"(srcA), "l"(dstB), "r"(srcB) : "memory");
                    asm volatile("cp.async.bulk.commit_group;");
                }
            }
        }
    }
    // Drain outstanding bulk stores before the staging smem dies with the CTA.
    asm volatile("cp.async.bulk.wait_group 0;");
}

extern "C" void kernel_launch(void* const* d_in, const int* in_sizes, int n_in,
                              void* d_out, int out_size) {
    const float* x = (const float*)d_in[0];
    float*       y = (float*)d_out;
    // 1024 planes * 4 chunks = 4096 warps; 4 warps/block -> 1024 blocks
    hexpool_kernel<<<1024, 128>>>(x, y);
}

// round 11
// speedup vs baseline: 1.0191x; 1.0191x over previous
#include <cuda_runtime.h>
#include <cstdint>

#define NEG_INF __int_as_float(0xff800000)

static __device__ __forceinline__ float max5(float a, float b, float c, float d, float e) {
    return fmaxf(fmaxf(a, fmaxf(b, c)), fmaxf(d, e));
}

// Hex maxpool, SIZE=2, STRIDE=1, plane = 256x256 fp32.
//   even w: col w rows [h-2,h+2]; cols w+-1 rows [h-2,h+1]; cols w+-2 rows [h-1,h+1]
//   odd  w: col w rows [h-2,h+2]; cols w+-1 rows [h-1,h+2]; cols w+-2 rows [h-1,h+1]
//
// Measured-best configuration (R6) + validated cleanups:
//   One warp per 256-wide strip of 64 rows; lane owns 8 columns.
//   Reads : cp.async (LDGSTS) into a 6-row smem ring, 5 rows in flight.
//           Rows CLAMPED to [0,255] — equivalent to -inf padding for max
//           (edge row is already a member of every affected sub-window).
//   Writes: 4 computed rows staged in smem, fired as one 4KB cp.async.bulk
//           burst, double-buffered (wait_group 1 -> never blocks in steady
//           state). 4KB is the measured sweet spot: 2KB and 8KB both lose.
//   4 warps/CTA, 56KB smem -> 4 CTAs/SM, 16 warps/SM (measured plateau).
__global__ __launch_bounds__(128, 4)
void hexpool_kernel(const float* __restrict__ x, float* __restrict__ y) {
    __shared__ float inring[4][6][256];                   // 24KB input rings
    __shared__ __align__(16) float ostage[4][2][4][256];  // 32KB store staging

    const int wid  = threadIdx.x >> 5;
    const int lane = threadIdx.x & 31;
    const int warp_global = blockIdx.x * 4 + wid;
    const int img   = warp_global >> 2;   // 1024 planes (N*C)
    const int chunk = warp_global & 3;    // 4 chunks of 64 rows
    const int h0    = chunk * 64;

    const float* __restrict__ inp = x + (size_t)img * 65536;
    const float* __restrict__ inl = inp + lane * 8;
    float* __restrict__ outbase   = y + (size_t)img * 65536;
    float* wring = &inring[wid][0][0];

    // Register window: row m in slot (m+2)&7 (compile-time under 8x unroll).
    float win[8][8];

    // Vertical clamp == -inf padding for this max window (verified R8).
    auto clamp_row = [&](int m) {
        int g = h0 + m;
        return g < 0 ? 0 : (g > 255 ? 255 : g);
    };

    auto load_row_g = [&](int m, float* dst) {
        const float* p = inl + (size_t)clamp_row(m) * 256;
        const float4 a = *reinterpret_cast<const float4*>(p);
        const float4 b = *reinterpret_cast<const float4*>(p + 4);
        dst[0] = a.x; dst[1] = a.y; dst[2] = a.z; dst[3] = a.w;
        dst[4] = b.x; dst[5] = b.y; dst[6] = b.z; dst[7] = b.w;
    };

    // Prefetch local row r (clamped) into ring slot r%6. Unconditional: one
    // LDGSTS pair + one commit per call keeps wait_group counting uniform.
    auto prefetch = [&](int r) {
        float* s = wring + (r % 6) * 256 + lane * 8;
        const float* gp = inp + (size_t)clamp_row(r) * 256 + lane * 8;
        uint32_t sa = (uint32_t)__cvta_generic_to_shared(s);
        asm volatile(
            "cp.async.cg.shared.global [%0], [%1], 16;\n\t"
            "cp.async.cg.shared.global [%2], [%3], 16;\n\t"
            "cp.async.commit_group;\n\t"
            :: "r"(sa), "l"(gp), "r"(sa + 16), "l"(gp + 4));
    };

    auto lds_row = [&](int r, float* dst) {
        const float* s = wring + (r % 6) * 256 + lane * 8;
        const float4 a = *reinterpret_cast<const float4*>(s);
        const float4 b = *reinterpret_cast<const float4*>(s + 4);
        dst[0] = a.x; dst[1] = a.y; dst[2] = a.z; dst[3] = a.w;
        dst[4] = b.x; dst[5] = b.y; dst[6] = b.z; dst[7] = b.w;
    };

    // Prologue: rows -2..2 -> registers; rows 3..7 into the async ring.
    #pragma unroll
    for (int m = -2; m <= 2; ++m) load_row_g(m, win[(m + 2) & 7]);
    #pragma unroll
    for (int r = 3; r <= 7; ++r) prefetch(r);

    for (int hh = 0; hh < 64; hh += 8) {
        #pragma unroll
        for (int u = 0; u < 8; ++u) {
            const int l = hh + u;

            if ((u & 3) == 0) {
                // About to refill the staging buffer whose burst was issued
                // 2 groups ago: allow at most 1 pending store group.
                asm volatile("cp.async.bulk.wait_group 1;");
            }

            // Read pipe: keep rows l+4..l+8 pending, pull row l+3 to regs.
            // (Past the strip edge this loads clamped row 255 into a slot
            //  that is never consumed — guard-free.)
            prefetch(l + 8);
            asm volatile("cp.async.wait_group 5;");
            lds_row(l + 3, win[(u + 5) & 7]);

            const int s0 = (u + 0) & 7;  // row l-2
            const int s1 = (u + 1) & 7;  // row l-1
            const int sc = (u + 2) & 7;  // row l
            const int s3 = (u + 3) & 7;  // row l+1
            const int s4 = (u + 4) & 7;  // row l+2

            float m3[8], A[8], m5v[8];
            #pragma unroll
            for (int j = 0; j < 8; ++j)
                m3[j] = fmaxf(fmaxf(win[s1][j], win[sc][j]), win[s3][j]);

            // parity of global col = j&1.
            //   odd  w: A = rows [h-2,h+1] = max(m3, r_{l-2})
            //   even w: A = rows [h-1,h+2] = max(m3, r_{l+2})
            //   m5 = 5-row max = max(A, remaining row)
            #pragma unroll
            for (int j = 0; j < 8; ++j) {
                if (j & 1) { A[j]   = fmaxf(m3[j], win[s0][j]);
                             m5v[j] = fmaxf(A[j], win[s4][j]); }
                else       { A[j]   = fmaxf(m3[j], win[s4][j]);
                             m5v[j] = fmaxf(A[j], win[s0][j]); }
            }

            // Horizontal halo across lanes
            float A_l   = __shfl_up_sync(0xffffffffu, A[7], 1);
            float m3_l2 = __shfl_up_sync(0xffffffffu, m3[6], 1);
            float m3_l1 = __shfl_up_sync(0xffffffffu, m3[7], 1);
            float A_r   = __shfl_down_sync(0xffffffffu, A[0], 1);
            float m3_r1 = __shfl_down_sync(0xffffffffu, m3[0], 1);
            float m3_r2 = __shfl_down_sync(0xffffffffu, m3[1], 1);
            if (lane == 0)  { A_l = NEG_INF; m3_l1 = NEG_INF; m3_l2 = NEG_INF; }
            if (lane == 31) { A_r = NEG_INF; m3_r1 = NEG_INF; m3_r2 = NEG_INF; }

            float4 v0, v1;
            v0.x = max5(m5v[0], A_l,  A[1], m3_l2, m3[2]);
            v0.y = max5(m5v[1], A[0], A[2], m3_l1, m3[3]);
            v0.z = max5(m5v[2], A[1], A[3], m3[0], m3[4]);
            v0.w = max5(m5v[3], A[2], A[4], m3[1], m3[5]);
            v1.x = max5(m5v[4], A[3], A[5], m3[2], m3[6]);
            v1.y = max5(m5v[5], A[4], A[6], m3[3], m3[7]);
            v1.z = max5(m5v[6], A[5], A[7], m3[4], m3_r1);
            v1.w = max5(m5v[7], A[6], A_r,  m3[5], m3_r2);

            // Stage the row; buf = (l>>2)&1.
            float* st = &ostage[wid][(l >> 2) & 1][l & 3][lane * 8];
            *reinterpret_cast<float4*>(st)     = v0;
            *reinterpret_cast<float4*>(st + 4) = v1;

            if ((u & 3) == 3) {
                // 4 rows (l-3..l) staged -> one 4KB bulk store burst.
                __syncwarp();
                if (lane == 0) {
                    asm volatile("fence.proxy.async.shared::cta;");
                    uint32_t src = (uint32_t)__cvta_generic_to_shared(
                        &ostage[wid][(l >> 2) & 1][0][0]);
                    float* dst = outbase + (size_t)(h0 + l - 3) * 256;
                    asm volatile(
                        "cp.async.bulk.global.shared::cta.bulk_group [%0], [%1], 4096;"
                        :: "l"(dst), "r"(src) : "memory");
                    asm volatile("cp.async.bulk.commit_group;");
                }
            }
        }
    }
    // Drain outstanding bulk stores before the staging smem dies with the CTA.
    asm volatile("cp.async.bulk.wait_group 0;");
}

extern "C" void kernel_launch(void* const* d_in, const int* in_sizes, int n_in,
                              void* d_out, int out_size) {
    const float* x = (const float*)d_in[0];
    float*       y = (float*)d_out;
    // 1024 planes * 4 chunks = 4096 warps; 4 warps/block -> 1024 blocks
    // (6.92 CTAs/SM sequential -> near-perfect wave balance).
    hexpool_kernel<<<1024, 128>>>(x, y);
}

// round 12
// speedup vs baseline: 1.0393x; 1.0198x over previous
#include <cuda_runtime.h>
#include <cstdint>

#define NEG_INF __int_as_float(0xff800000)

static __device__ __forceinline__ float max5(float a, float b, float c, float d, float e) {
    return fmaxf(fmaxf(a, fmaxf(b, c)), fmaxf(d, e));
}

// Hex maxpool, SIZE=2, STRIDE=1, plane = 256x256 fp32.
//   even w: col w rows [h-2,h+2]; cols w+-1 rows [h-2,h+1]; cols w+-2 rows [h-1,h+1]
//   odd  w: col w rows [h-2,h+2]; cols w+-1 rows [h-1,h+2]; cols w+-2 rows [h-1,h+1]
//
// Convergent configuration (R6 bytes + R11 efficiency):
//   One warp per 256-wide strip of 64 rows; lane owns 8 columns.
//   Reads : cp.async (LDGSTS) into a 6-row smem ring, 5 rows in flight,
//           rows clamped to [0,255] (== -inf padding for max, verified R8).
//           Data issued ONLY for rows <= 65 (R11's unconditional prefetch
//           added ~4% traffic); empty commits keep wait_group counts uniform.
//   Writes: 4 computed rows staged in smem, fired as one 4KB cp.async.bulk
//           burst, double-buffered (4KB measured optimal: 2KB & 8KB lose).
//   4 warps/CTA, 56KB smem -> 4 CTAs/SM, 16 warps/SM (measured plateau).
__global__ __launch_bounds__(128, 4)
void hexpool_kernel(const float* __restrict__ x, float* __restrict__ y) {
    __shared__ float inring[4][6][256];                   // 24KB input rings
    __shared__ __align__(16) float ostage[4][2][4][256];  // 32KB store staging

    const int wid  = threadIdx.x >> 5;
    const int lane = threadIdx.x & 31;
    const int warp_global = blockIdx.x * 4 + wid;
    const int img   = warp_global >> 2;   // 1024 planes (N*C)
    const int chunk = warp_global & 3;    // 4 chunks of 64 rows
    const int h0    = chunk * 64;

    const float* __restrict__ inp = x + (size_t)img * 65536;
    const float* __restrict__ inl = inp + lane * 8;
    float* __restrict__ outbase   = y + (size_t)img * 65536;
    float* wring = &inring[wid][0][0];

    // Register window: row m in slot (m+2)&7 (compile-time under 8x unroll).
    float win[8][8];

    // Vertical clamp == -inf padding for this max window (verified R8).
    auto clamp_row = [&](int m) {
        int g = h0 + m;
        return g < 0 ? 0 : (g > 255 ? 255 : g);
    };

    auto load_row_g = [&](int m, float* dst) {
        const float* p = inl + (size_t)clamp_row(m) * 256;
        const float4 a = *reinterpret_cast<const float4*>(p);
        const float4 b = *reinterpret_cast<const float4*>(p + 4);
        dst[0] = a.x; dst[1] = a.y; dst[2] = a.z; dst[3] = a.w;
        dst[4] = b.x; dst[5] = b.y; dst[6] = b.z; dst[7] = b.w;
    };

    // Prefetch local row r (clamped) into ring slot r%6 — but only rows that
    // are actually consumed (r <= 65). ALWAYS commits exactly one group so
    // wait_group counting stays uniform.
    auto prefetch = [&](int r) {
        if (r <= 65) {
            float* s = wring + (r % 6) * 256 + lane * 8;
            const float* gp = inp + (size_t)clamp_row(r) * 256 + lane * 8;
            uint32_t sa = (uint32_t)__cvta_generic_to_shared(s);
            asm volatile(
                "cp.async.cg.shared.global [%0], [%1], 16;\n\t"
                "cp.async.cg.shared.global [%2], [%3], 16;\n\t"
                :: "r"(sa), "l"(gp), "r"(sa + 16), "l"(gp + 4));
        }
        asm volatile("cp.async.commit_group;");
    };

    auto lds_row = [&](int r, float* dst) {
        const float* s = wring + (r % 6) * 256 + lane * 8;
        const float4 a = *reinterpret_cast<const float4*>(s);
        const float4 b = *reinterpret_cast<const float4*>(s + 4);
        dst[0] = a.x; dst[1] = a.y; dst[2] = a.z; dst[3] = a.w;
        dst[4] = b.x; dst[5] = b.y; dst[6] = b.z; dst[7] = b.w;
    };

    // Prologue: rows -2..2 -> registers; rows 3..7 into the async ring.
    #pragma unroll
    for (int m = -2; m <= 2; ++m) load_row_g(m, win[(m + 2) & 7]);
    #pragma unroll
    for (int r = 3; r <= 7; ++r) prefetch(r);

    for (int hh = 0; hh < 64; hh += 8) {
        #pragma unroll
        for (int u = 0; u < 8; ++u) {
            const int l = hh + u;

            if ((u & 3) == 0) {
                // About to refill the staging buffer whose burst was issued
                // 2 groups ago: allow at most 1 pending store group.
                asm volatile("cp.async.bulk.wait_group 1;");
            }

            // Read pipe: keep rows l+4..l+8 pending, pull row l+3 to regs.
            prefetch(l + 8);
            asm volatile("cp.async.wait_group 5;");
            if (l < 63) lds_row(l + 3, win[(u + 5) & 7]);

            const int s0 = (u + 0) & 7;  // row l-2
            const int s1 = (u + 1) & 7;  // row l-1
            const int sc = (u + 2) & 7;  // row l
            const int s3 = (u + 3) & 7;  // row l+1
            const int s4 = (u + 4) & 7;  // row l+2

            float m3[8], A[8], m5v[8];
            #pragma unroll
            for (int j = 0; j < 8; ++j)
                m3[j] = fmaxf(fmaxf(win[s1][j], win[sc][j]), win[s3][j]);

            // parity of global col = j&1.
            //   odd  w: A = rows [h-2,h+1] = max(m3, r_{l-2})
            //   even w: A = rows [h-1,h+2] = max(m3, r_{l+2})
            //   m5 = 5-row max = max(A, remaining row)
            #pragma unroll
            for (int j = 0; j < 8; ++j) {
                if (j & 1) { A[j]   = fmaxf(m3[j], win[s0][j]);
                             m5v[j] = fmaxf(A[j], win[s4][j]); }
                else       { A[j]   = fmaxf(m3[j], win[s4][j]);
                             m5v[j] = fmaxf(A[j], win[s0][j]); }
            }

            // Horizontal halo across lanes
            float A_l   = __shfl_up_sync(0xffffffffu, A[7], 1);
            float m3_l2 = __shfl_up_sync(0xffffffffu, m3[6], 1);
            float m3_l1 = __shfl_up_sync(0xffffffffu, m3[7], 1);
            float A_r   = __shfl_down_sync(0xffffffffu, A[0], 1);
            float m3_r1 = __shfl_down_sync(0xffffffffu, m3[0], 1);
            float m3_r2 = __shfl_down_sync(0xffffffffu, m3[1], 1);
            if (lane == 0)  { A_l = NEG_INF; m3_l1 = NEG_INF; m3_l2 = NEG_INF; }
            if (lane == 31) { A_r = NEG_INF; m3_r1 = NEG_INF; m3_r2 = NEG_INF; }

            float4 v0, v1;
            v0.x = max5(m5v[0], A_l,  A[1], m3_l2, m3[2]);
            v0.y = max5(m5v[1], A[0], A[2], m3_l1, m3[3]);
            v0.z = max5(m5v[2], A[1], A[3], m3[0], m3[4]);
            v0.w = max5(m5v[3], A[2], A[4], m3[1], m3[5]);
            v1.x = max5(m5v[4], A[3], A[5], m3[2], m3[6]);
            v1.y = max5(m5v[5], A[4], A[6], m3[3], m3[7]);
            v1.z = max5(m5v[6], A[5], A[7], m3[4], m3_r1);
            v1.w = max5(m5v[7], A[6], A_r,  m3[5], m3_r2);

            // Stage the row; buf = (l>>2)&1.
            float* st = &ostage[wid][(l >> 2) & 1][l & 3][lane * 8];
            *reinterpret_cast<float4*>(st)     = v0;
            *reinterpret_cast<float4*>(st + 4) = v1;

            if ((u & 3) == 3) {
                // 4 rows (l-3..l) staged -> one 4KB bulk store burst.
                __syncwarp();
                if (lane == 0) {
                    asm volatile("fence.proxy.async.shared::cta;");
                    uint32_t src = (uint32_t)__cvta_generic_to_shared(
                        &ostage[wid][(l >> 2) & 1][0][0]);
                    float* dst = outbase + (size_t)(h0 + l - 3) * 256;
                    asm volatile(
                        "cp.async.bulk.global.shared::cta.bulk_group [%0], [%1], 4096;"
                        :: "l"(dst), "r"(src) : "memory");
                    asm volatile("cp.async.bulk.commit_group;");
                }
            }
        }
    }
    // Drain outstanding bulk stores before the staging smem dies with the CTA.
    asm volatile("cp.async.bulk.wait_group 0;");
}

extern "C" void kernel_launch(void* const* d_in, const int* in_sizes, int n_in,
                              void* d_out, int out_size) {
    const float* x = (const float*)d_in[0];
    float*       y = (float*)d_out;
    // 1024 planes * 4 chunks = 4096 warps; 4 warps/block -> 1024 blocks
    hexpool_kernel<<<1024, 128>>>(x, y);
}